// round 8
// baseline (speedup 1.0000x reference)
#include <cuda_runtime.h>
#include <math.h>

#define VOCAB 50257
#define BATCH 512
#define SEQ   512
#define EMBED 256
#define OUTC  5
#define EV4   (EMBED / 4)   // 64 float4 per embedding row
#define PROJ_STRIDE 8       // padded floats per vocab entry (32 B aligned)
#define GRID  592           // 148 SMs x 4 CTAs: entire grid co-resident

// Device scratch (mallocs forbidden). Counters zero at load and reset
// in-kernel every call -> graph-replay safe.
__device__ float        g_proj[(size_t)VOCAB * PROJ_STRIDE];  // ~1.6 MB
__device__ float        g_loss[BATCH];
__device__ unsigned int g_arrive;   // grid-barrier arrivals
__device__ unsigned int g_done;     // grid-barrier departures (guards reset)
__device__ unsigned int g_count;    // phase-2 sample completions

__global__ __launch_bounds__(256, 4)
void fused_kernel(const int*   __restrict__ input_x,
                  const int*   __restrict__ lengths,
                  const int*   __restrict__ input_y,
                  const float* __restrict__ emb,
                  const float* __restrict__ W,
                  const float* __restrict__ bias,
                  float*       __restrict__ out)
{
    __shared__ float s_red[8][OUTC];
    __shared__ float s_sum[256];
    __shared__ int   s_last;

    const int tid  = threadIdx.x;
    const int lane = tid & 31;
    const int wid  = tid >> 5;

    // ================= Phase 1: proj[v][o] = emb[v,:] . W[o,:] =============
    {
        const float4* __restrict__ embv = (const float4*)emb;
        const float4* __restrict__ Wv   = (const float4*)W;

        // Per-lane W slices: 2 float4 per output (40 regs)
        float4 w0[OUTC], w1[OUTC];
        #pragma unroll
        for (int o = 0; o < OUTC; o++) {
            w0[o] = Wv[o * EV4 + lane];
            w1[o] = Wv[o * EV4 + 32 + lane];
        }

        const int gw     = (blockIdx.x << 3) + wid;   // global warp id
        const int nwarps = GRID * 8;                  // 4736

        for (int row = gw; row < VOCAB; row += nwarps) {
            float4 a0 = embv[(long)row * EV4 + lane];
            float4 a1 = embv[(long)row * EV4 + 32 + lane];
            float acc[OUTC];
            #pragma unroll
            for (int o = 0; o < OUTC; o++) {
                acc[o] = a0.x * w0[o].x + a0.y * w0[o].y
                       + a0.z * w0[o].z + a0.w * w0[o].w
                       + a1.x * w1[o].x + a1.y * w1[o].y
                       + a1.z * w1[o].z + a1.w * w1[o].w;
            }
            #pragma unroll
            for (int o = 0; o < OUTC; o++) {
                #pragma unroll
                for (int off = 16; off > 0; off >>= 1)
                    acc[o] += __shfl_down_sync(0xffffffffu, acc[o], off);
            }
            if (lane == 0) {
                *(float4*)&g_proj[(long)row * PROJ_STRIDE] =
                    make_float4(acc[0], acc[1], acc[2], acc[3]);
                g_proj[(long)row * PROJ_STRIDE + 4] = acc[4];
            }
        }
    }

    // ================= Grid-wide barrier (all 592 CTAs resident) ===========
    __threadfence();            // release: publish g_proj writes
    __syncthreads();
    if (tid == 0) {
        atomicAdd(&g_arrive, 1u);
        while (*(volatile unsigned int*)&g_arrive < GRID) __nanosleep(64);
        // Departure count guards the reset: only after ALL CTAs have passed
        // the spin may the counters be cleared for the next graph replay.
        if (atomicAdd(&g_done, 1u) == GRID - 1) {
            g_arrive = 0;
            g_done   = 0;
        }
    }
    __syncthreads();
    __threadfence();            // acquire: order g_proj reads after barrier

    // ================= Phase 2: per-sample loss (CTAs 0..511) ==============
    const int b = blockIdx.x;
    if (b >= BATCH) return;

    const int len = lengths[b];
    const int* xrow = input_x + b * SEQ;

    float acc[OUTC];
    #pragma unroll
    for (int o = 0; o < OUTC; o++) acc[o] = 0.f;

    if (tid < len) {
        const int t = xrow[tid];
        float4 p = *(const float4*)&g_proj[(long)t * PROJ_STRIDE];
        float  q = g_proj[(long)t * PROJ_STRIDE + 4];
        acc[0] += p.x; acc[1] += p.y; acc[2] += p.z; acc[3] += p.w; acc[4] += q;
    }
    if (tid + 256 < len) {
        const int t = xrow[tid + 256];
        float4 p = *(const float4*)&g_proj[(long)t * PROJ_STRIDE];
        float  q = g_proj[(long)t * PROJ_STRIDE + 4];
        acc[0] += p.x; acc[1] += p.y; acc[2] += p.z; acc[3] += p.w; acc[4] += q;
    }

    #pragma unroll
    for (int o = 0; o < OUTC; o++) {
        #pragma unroll
        for (int off = 16; off > 0; off >>= 1)
            acc[o] += __shfl_down_sync(0xffffffffu, acc[o], off);
    }
    if (lane == 0) {
        #pragma unroll
        for (int o = 0; o < OUTC; o++) s_red[wid][o] = acc[o];
    }
    __syncthreads();

    if (tid == 0) {
        float tot[OUTC];
        #pragma unroll
        for (int o = 0; o < OUTC; o++) {
            tot[o] = ((s_red[0][o] + s_red[1][o]) + (s_red[2][o] + s_red[3][o]))
                   + ((s_red[4][o] + s_red[5][o]) + (s_red[6][o] + s_red[7][o]));
        }
        const float inv_len = 1.0f / (float)len;
        float logits[OUTC];
        float m = -INFINITY;
        #pragma unroll
        for (int o = 0; o < OUTC; o++) {
            logits[o] = tot[o] * inv_len + bias[o];
            m = fmaxf(m, logits[o]);
        }
        float se = 0.f;
        #pragma unroll
        for (int o = 0; o < OUTC; o++) se += __expf(logits[o] - m);
        const float lse = m + __logf(se);
        const int y = input_y[b];
        g_loss[b] = lse - logits[y];
        __threadfence();
        s_last = (atomicAdd(&g_count, 1u) == BATCH - 1) ? 1 : 0;
    }
    __syncthreads();

    // Last sample-CTA: mean over the 512 losses
    if (s_last) {
        __threadfence();
        s_sum[tid] = g_loss[tid] + g_loss[tid + 256];
        __syncthreads();
        #pragma unroll
        for (int off = 128; off > 0; off >>= 1) {
            if (tid < off) s_sum[tid] += s_sum[tid + off];
            __syncthreads();
        }
        if (tid == 0) {
            out[0] = s_sum[0] * (1.0f / (float)BATCH);
            g_count = 0;   // reset for next replay
        }
    }
}

extern "C" void kernel_launch(void* const* d_in, const int* in_sizes, int n_in,
                              void* d_out, int out_size)
{
    const int*   input_x = (const int*)d_in[0];
    const int*   lengths = (const int*)d_in[1];
    const int*   input_y = (const int*)d_in[2];
    const float* emb     = (const float*)d_in[3];
    const float* W       = (const float*)d_in[4];
    const float* bias    = (const float*)d_in[5];
    float* out = (float*)d_out;

    fused_kernel<<<GRID, 256>>>(input_x, lengths, input_y, emb, W, bias, out);
}